// round 6
// baseline (speedup 1.0000x reference)
#include <cuda_runtime.h>
#include <cstdint>

#define D 128
#define C 64
#define EPSF 1e-5f
#define TGT 32            // targets per CTA  -> grid = 16384/32 = 512
#define XS_STRIDE 132

// q[c][j] = EPS - prototype[c][j]   (device scratch; allocations forbidden)
__device__ float g_q[C * D];

__device__ __forceinline__ void add_f32x2(unsigned long long& d,
                                          unsigned long long a,
                                          unsigned long long b) {
    asm("add.rn.f32x2 %0, %1, %2;" : "=l"(d) : "l"(a), "l"(b));
}
__device__ __forceinline__ void fma_f32x2(unsigned long long& d,
                                          unsigned long long a,
                                          unsigned long long b) {
    asm("fma.rn.f32x2 %0, %1, %2, %0;" : "+l"(d) : "l"(a), "l"(b));
}

// ---------------------------------------------------------------------------
// Kernel 1 (unchanged from R5): one CTA per class; gather row list, coalesced
// register accumulation, writes finalized q = EPS - sum/cnt'. No global atomics.
// ---------------------------------------------------------------------------
__global__ __launch_bounds__(256) void k_accum(const float* __restrict__ x,
                                               const int* __restrict__ y,
                                               float* __restrict__ out,
                                               int m) {
    __shared__ unsigned short list[4096];
    __shared__ int cnt;
    __shared__ float partial[D];

    int tid = threadIdx.x;
    int c   = blockIdx.x;
    if (tid == 0) cnt = 0;
    if (c == 0 && tid == 0) out[0] = 0.0f;
    __syncthreads();

    for (int i = tid; i < m; i += 256) {
        if (y[i] == c) {
            int p = atomicAdd(&cnt, 1);
            if (p < 4096) list[p] = (unsigned short)i;
        }
    }
    __syncthreads();
    int n = cnt < 4096 ? cnt : 4096;

    int j    = tid & (D - 1);
    int half = tid >> 7;
    float acc = 0.0f;
#pragma unroll 4
    for (int k = half; k < n; k += 2) {
        acc += x[(size_t)list[k] * D + j];
    }
    if (half == 1) partial[j] = acc;
    __syncthreads();
    if (half == 0) {
        float tot = acc + partial[j];
        float fc  = (n == 0) ? 1.0f : (float)n;
        g_q[c * D + j] = EPSF - tot / fc;
    }
}

// ---------------------------------------------------------------------------
// Kernel 2: distances + log_softmax + NLL, packed f32x2 mainloop.
// 256 threads = 32 targets x 8 class-groups of 8. cg = warp-id -> q LDS
// broadcasts. x staged in smem (stride 132 floats: conflict-free 16B loads).
// smem ~49.7KB -> up to 4 CTAs/SM; grid 512 -> ~3.5 resident (occ ~43%).
// ---------------------------------------------------------------------------
extern __shared__ float smem[];

__global__ __launch_bounds__(256, 4) void k_loss(const float* __restrict__ x,
                                                 const int* __restrict__ y,
                                                 float* __restrict__ out,
                                                 int m) {
    float* xs = smem;                  // TGT * 132
    float* qs = xs + TGT * XS_STRIDE;  // 64 * 128
    __shared__ float spmax[8 * TGT];
    __shared__ float spsum[8 * TGT];
    __shared__ float sdy[TGT];
    __shared__ float red[TGT];

    int tid = threadIdx.x;
    int i0  = blockIdx.x * TGT;

    // stage x target tile (coalesced float4)
    const float4* xg = (const float4*)(x + (size_t)(m + i0) * D);
    for (int idx = tid; idx < TGT * (D / 4); idx += 256) {
        int r  = idx >> 5;
        int c4 = idx & 31;
        *(float4*)&xs[r * XS_STRIDE + c4 * 4] = xg[r * (D / 4) + c4];
    }
    // stage q tile (L2-resident after first CTA)
    for (int idx = tid; idx < C * D / 4; idx += 256) {
        ((float4*)qs)[idx] = ((const float4*)g_q)[idx];
    }
    __syncthreads();

    int tgt = tid & 31;
    int cg  = tid >> 5;                // == warp id -> uniform per warp
    const ulonglong2* xrow = (const ulonglong2*)&xs[tgt * XS_STRIDE];
    const float* qb = &qs[cg * 8 * D];

    unsigned long long acc[8];
#pragma unroll
    for (int k = 0; k < 8; k++) acc[k] = 0ull;

    const unsigned long long ABS2 = 0x7FFFFFFF7FFFFFFFull;

    for (int j4 = 0; j4 < D / 4; j4++) {
        ulonglong2 xv = xrow[j4];
#pragma unroll
        for (int cc = 0; cc < 8; cc++) {
            ulonglong2 qv = *(const ulonglong2*)&qb[cc * D + j4 * 4];
            unsigned long long t01, t23;
            add_f32x2(t01, xv.x, qv.x);            // t = x + (EPS - p)
            add_f32x2(t23, xv.y, qv.y);
            unsigned long long a01 = t01 & ABS2;   // |t| on alu pipe
            unsigned long long a23 = t23 & ABS2;
            fma_f32x2(acc[cc], t01, a01);          // acc += t * |t|
            fma_f32x2(acc[cc], t23, a23);
        }
    }

    // unpack, partial softmax over this thread's 8 classes
    float dist[8];
    float pm = -1e30f;
#pragma unroll
    for (int cc = 0; cc < 8; cc++) {
        float lo = __uint_as_float((unsigned)(acc[cc] & 0xFFFFFFFFull));
        float hi = __uint_as_float((unsigned)(acc[cc] >> 32));
        float dv = (lo + hi) * (-1.0f / (float)D);
        dist[cc] = dv;
        pm = fmaxf(pm, dv);
    }
    spmax[cg * TGT + tgt] = pm;
    __syncthreads();

    float gmax = -1e30f;
#pragma unroll
    for (int k = 0; k < 8; k++) gmax = fmaxf(gmax, spmax[k * TGT + tgt]);

    float se = 0.0f;
#pragma unroll
    for (int cc = 0; cc < 8; cc++) se += __expf(dist[cc] - gmax);
    spsum[cg * TGT + tgt] = se;

    int yc = y[m + i0 + tgt];
    if ((yc >> 3) == cg) sdy[tgt] = dist[yc & 7];
    __syncthreads();

    if (tid < TGT) {
        float tot = 0.0f;
#pragma unroll
        for (int k = 0; k < 8; k++) tot += spsum[k * TGT + tid];
        red[tid] = -(sdy[tid] - gmax - __logf(tot));
    }
    __syncthreads();

    if (tid == 0) {
        float s = 0.0f;
#pragma unroll 8
        for (int k = 0; k < TGT; k++) s += red[k];
        atomicAdd(out, s / (float)m);
    }
}

// ---------------------------------------------------------------------------
// launch
// ---------------------------------------------------------------------------
extern "C" void kernel_launch(void* const* d_in, const int* in_sizes, int n_in,
                              void* d_out, int out_size) {
    const float* x = (const float*)d_in[0];
    const int*   y = (const int*)d_in[1];
    int n = in_sizes[1];
    int m = n / 2;
    float* out = (float*)d_out;

    k_accum<<<C, 256>>>(x, y, out, m);

    size_t dynbytes = (size_t)(TGT * XS_STRIDE + C * D) * sizeof(float);
    cudaFuncSetAttribute(k_loss, cudaFuncAttributeMaxDynamicSharedMemorySize,
                         (int)dynbytes);
    k_loss<<<m / TGT, 256, dynbytes>>>(x, y, out, m);
}